// round 10
// baseline (speedup 1.0000x reference)
#include <cuda_runtime.h>
#include <cuda_bf16.h>
#include <math.h>
#include <stdint.h>
#include <mma.h>

using namespace nvcuda;

#define ND 100000
#define NP 100000
#define EE 800000

// ---------------- scratch (__device__ globals; no allocations) ----------------
__device__ float g_fs_dp[ND * 128];
__device__ float g_fs_pd[NP * 128];
__device__ float g_agg_p[NP * 128];
__device__ float g_agg_d[ND * 128];
__device__ float g_el_dp[ND * 4];
__device__ float g_er_dp[NP * 4];
__device__ float g_el_pd[NP * 4];
__device__ float g_er_pd[ND * 4];
__device__ float g_s_p[NP * 4];
__device__ float g_s_d[ND * 4];
__device__ float g_ex_dp[EE * 4];
__device__ float g_ex_pd[EE * 4];

// ---------------- helpers ----------------
__device__ __forceinline__ void red_add_v4(float* addr, float4 v) {
    asm volatile("red.global.add.v4.f32 [%0], {%1,%2,%3,%4};"
                 :: "l"(addr), "f"(v.x), "f"(v.y), "f"(v.z), "f"(v.w) : "memory");
}
__device__ __forceinline__ float lrelu_exp(float v) {
    // leaky_relu(v,0.2) then exp; softmax max-shift omitted (shift-invariant, |e| = O(1))
    return expf(v > 0.f ? v : 0.2f * v);
}

// split v into bf16 hi + bf16 lo (v ~= hi + lo), store 4 consecutive
__device__ __forceinline__ void split4(float4 v, __nv_bfloat16* hi, __nv_bfloat16* lo) {
    __nv_bfloat16 h0 = __float2bfloat16(v.x);
    __nv_bfloat16 h1 = __float2bfloat16(v.y);
    __nv_bfloat16 h2 = __float2bfloat16(v.z);
    __nv_bfloat16 h3 = __float2bfloat16(v.w);
    __nv_bfloat16 l0 = __float2bfloat16(v.x - __bfloat162float(h0));
    __nv_bfloat16 l1 = __float2bfloat16(v.y - __bfloat162float(h1));
    __nv_bfloat16 l2 = __float2bfloat16(v.z - __bfloat162float(h2));
    __nv_bfloat16 l3 = __float2bfloat16(v.w - __bfloat162float(h3));
    __nv_bfloat162* H = (__nv_bfloat162*)hi;
    __nv_bfloat162* L = (__nv_bfloat162*)lo;
    H[0] = __nv_bfloat162(h0, h1); H[1] = __nv_bfloat162(h2, h3);
    L[0] = __nv_bfloat162(l0, l1); L[1] = __nv_bfloat162(l2, l3);
}

#define BLD 136          // bf16 smem row stride (halves)
#define STG_LD 132       // f32 staging row stride (floats), avoids bank conflicts

// 3-term split mainloop: acc += Ahi*Bhi + Ahi*Blo + Alo*Bhi   (warp covers 16 rows x 128 cols)
__device__ __forceinline__ void mainloop3(
    wmma::fragment<wmma::accumulator, 16, 16, 16, float> (&acc)[8],
    const __nv_bfloat16* Ah, const __nv_bfloat16* Al,
    const __nv_bfloat16* Bh, const __nv_bfloat16* Bl, int warprow)
{
    #pragma unroll
    for (int ks = 0; ks < 8; ks++) {
        wmma::fragment<wmma::matrix_a, 16, 16, 16, __nv_bfloat16, wmma::row_major> ah, al;
        wmma::load_matrix_sync(ah, Ah + warprow * BLD + ks * 16, BLD);
        wmma::load_matrix_sync(al, Al + warprow * BLD + ks * 16, BLD);
        #pragma unroll
        for (int j = 0; j < 8; j++) {
            wmma::fragment<wmma::matrix_b, 16, 16, 16, __nv_bfloat16, wmma::row_major> bh, bl;
            wmma::load_matrix_sync(bh, Bh + (ks * 16) * BLD + j * 16, BLD);
            wmma::load_matrix_sync(bl, Bl + (ks * 16) * BLD + j * 16, BLD);
            wmma::mma_sync(acc[j], ah, bh, acc[j]);
            wmma::mma_sync(acc[j], ah, bl, acc[j]);
            wmma::mma_sync(acc[j], al, bh, acc[j]);
        }
    }
}

// ---------------- fused node kernel ----------------
// Per 128-row tile: T = relu(X@Win + b);  U = T@W1 -> write fs, el = headdot(U, al1);
// V = T@W2 -> er = headdot(V, ar2)  (V never written to global).
#define F_R1H 0                      // X / T hi (34816)
#define F_R1L 34816                  // X / T lo
#define F_R2H 69632                  // Win hi -> later f32 staging (128*132*4 = 67584)
#define F_R2L 104448                 // Win lo
#define F_STG 69632
#define F_R3H 139264                 // W1 / W2 hi
#define F_R3L 174080                 // W1 / W2 lo
#define F_BIAS 208896                // 16x128 f32
#define F_ATT 217088                 // al1[128], ar2[128] f32
#define F_SMEM 218112

__global__ void __launch_bounds__(256, 1)
fused_node(const float* __restrict__ X, const float* __restrict__ Win,
           const float* __restrict__ bin,
           const float* __restrict__ W1, const float* __restrict__ al1,
           const float* __restrict__ W2, const float* __restrict__ ar2,
           float* __restrict__ fs_out, float* __restrict__ el_out,
           float* __restrict__ er_out, int n)
{
    extern __shared__ char sm[];
    __nv_bfloat16* Ah = (__nv_bfloat16*)(sm + F_R1H);
    __nv_bfloat16* Al = (__nv_bfloat16*)(sm + F_R1L);
    __nv_bfloat16* WinH = (__nv_bfloat16*)(sm + F_R2H);
    __nv_bfloat16* WinL = (__nv_bfloat16*)(sm + F_R2L);
    __nv_bfloat16* WH = (__nv_bfloat16*)(sm + F_R3H);
    __nv_bfloat16* WL = (__nv_bfloat16*)(sm + F_R3L);
    float* STG = (float*)(sm + F_STG);
    float* biasT = (float*)(sm + F_BIAS);
    float* att = (float*)(sm + F_ATT);

    const int tid = threadIdx.x;
    const int warp = tid >> 5;
    const int warprow = warp * 16;
    const int rowbase = blockIdx.x * 128;

    // ---- phase 1: loads ----
    #pragma unroll
    for (int t = tid; t < 4096; t += 256) {            // Win 128x128
        int r = t >> 5, q = t & 31;
        float4 v = *(const float4*)(Win + (size_t)r * 128 + q * 4);
        split4(v, WinH + r * BLD + q * 4, WinL + r * BLD + q * 4);
    }
    #pragma unroll
    for (int t = tid; t < 4096; t += 256) {            // W1 128x128
        int r = t >> 5, q = t & 31;
        float4 v = *(const float4*)(W1 + (size_t)r * 128 + q * 4);
        split4(v, WH + r * BLD + q * 4, WL + r * BLD + q * 4);
    }
    #pragma unroll
    for (int t = tid; t < 4096; t += 256) {            // X tile (guarded)
        int r = t >> 5, q = t & 31;
        int gr = rowbase + r;
        float4 v = make_float4(0.f, 0.f, 0.f, 0.f);
        if (gr < n) v = *(const float4*)(X + (size_t)gr * 128 + q * 4);
        split4(v, Ah + r * BLD + q * 4, Al + r * BLD + q * 4);
    }
    #pragma unroll
    for (int t = tid; t < 2048; t += 256) biasT[t] = __ldg(bin + (t & 127));
    if (tid < 128) {
        att[tid] = __ldg(al1 + tid);
        att[128 + tid] = __ldg(ar2 + tid);
    }
    __syncthreads();

    // ---- phase 2: T = relu(X@Win + b) ----
    wmma::fragment<wmma::accumulator, 16, 16, 16, float> acc[8];
    #pragma unroll
    for (int j = 0; j < 8; j++)
        wmma::load_matrix_sync(acc[j], biasT + j * 16, 128, wmma::mem_row_major);
    mainloop3(acc, Ah, Al, WinH, WinL, warprow);
    #pragma unroll
    for (int j = 0; j < 8; j++)
        #pragma unroll
        for (int t = 0; t < acc[j].num_elements; t++)
            acc[j].x[t] = fmaxf(acc[j].x[t], 0.f);
    __syncthreads();                                    // mainloop done: R2 free for staging
    #pragma unroll
    for (int j = 0; j < 8; j++)
        wmma::store_matrix_sync(STG + warprow * STG_LD + j * 16, acc[j], STG_LD,
                                wmma::mem_row_major);
    __syncthreads();
    // split T into R1 (overwrite X)
    #pragma unroll
    for (int t = tid; t < 4096; t += 256) {
        int r = t >> 5, q = t & 31;
        float4 v = *(const float4*)(STG + r * STG_LD + q * 4);
        split4(v, Ah + r * BLD + q * 4, Al + r * BLD + q * 4);
    }
    __syncthreads();

    // ---- phase 3: U = T@W1 -> fs + el ----
    #pragma unroll
    for (int j = 0; j < 8; j++) wmma::fill_fragment(acc[j], 0.f);
    mainloop3(acc, Ah, Al, WH, WL, warprow);
    __syncthreads();
    #pragma unroll
    for (int j = 0; j < 8; j++)
        wmma::store_matrix_sync(STG + warprow * STG_LD + j * 16, acc[j], STG_LD,
                                wmma::mem_row_major);
    __syncthreads();
    #pragma unroll
    for (int t = tid; t < 4096; t += 256) {             // write fs (coalesced, guarded)
        int r = t >> 5, q = t & 31;
        int gr = rowbase + r;
        if (gr < n)
            *(float4*)(fs_out + (size_t)gr * 128 + q * 4) =
                *(const float4*)(STG + r * STG_LD + q * 4);
    }
    #pragma unroll
    for (int t = tid; t < 512; t += 256) {              // el = headdot(U, al1)
        int r = t >> 2, h = t & 3;
        int gr = rowbase + r;
        const float* row = STG + r * STG_LD + h * 32;
        const float* av = att + h * 32;
        float s = 0.f;
        #pragma unroll
        for (int d = 0; d < 32; d++) s += row[d] * av[d];
        if (gr < n) el_out[(size_t)gr * 4 + h] = s;
    }
    __syncthreads();

    // ---- phase 4: V = T@W2 -> er only ----
    #pragma unroll
    for (int t = tid; t < 4096; t += 256) {             // load W2 over R3
        int r = t >> 5, q = t & 31;
        float4 v = *(const float4*)(W2 + (size_t)r * 128 + q * 4);
        split4(v, WH + r * BLD + q * 4, WL + r * BLD + q * 4);
    }
    __syncthreads();
    #pragma unroll
    for (int j = 0; j < 8; j++) wmma::fill_fragment(acc[j], 0.f);
    mainloop3(acc, Ah, Al, WH, WL, warprow);
    __syncthreads();
    #pragma unroll
    for (int j = 0; j < 8; j++)
        wmma::store_matrix_sync(STG + warprow * STG_LD + j * 16, acc[j], STG_LD,
                                wmma::mem_row_major);
    __syncthreads();
    #pragma unroll
    for (int t = tid; t < 512; t += 256) {              // er = headdot(V, ar2)
        int r = t >> 2, h = t & 3;
        int gr = rowbase + r;
        const float* row = STG + r * STG_LD + h * 32;
        const float* av = att + 128 + h * 32;
        float s = 0.f;
        #pragma unroll
        for (int d = 0; d < 32; d++) s += row[d] * av[d];
        if (gr < n) er_out[(size_t)gr * 4 + h] = s;
    }
}

// ---------------- bf16 wmma GEMM (out-projections): C = A@B + bias ----------------
// CTA tile 256x128, K=128 resident, 8 warps, warp = 32 rows x 128 cols.
#define SM_BH 0
#define SM_BL (128 * BLD * 2)
#define SM_AH (2 * 128 * BLD * 2)
#define SM_AL (SM_AH + 256 * BLD * 2)
#define SM_BIAS (SM_AH + 2 * 256 * BLD * 2)
#define SM_EPI SM_AH
#define GW_SMEM (SM_BIAS + 16 * 128 * 4)

__global__ void __launch_bounds__(256, 1)
gemm_bf16(const float* __restrict__ A, const float* __restrict__ B,
          const float* __restrict__ bias, float* __restrict__ C, int n)
{
    extern __shared__ char sm[];
    __nv_bfloat16* Bh = (__nv_bfloat16*)(sm + SM_BH);
    __nv_bfloat16* Bl = (__nv_bfloat16*)(sm + SM_BL);
    __nv_bfloat16* Ah = (__nv_bfloat16*)(sm + SM_AH);
    __nv_bfloat16* Al = (__nv_bfloat16*)(sm + SM_AL);
    float* biasT = (float*)(sm + SM_BIAS);

    const int tid = threadIdx.x;
    const int warp = tid >> 5;
    const int lane = tid & 31;
    const int rowbase = blockIdx.x * 256;

    #pragma unroll
    for (int t = tid; t < 4096; t += 256) {
        int r = t >> 5, q = t & 31;
        float4 v = *(const float4*)(B + (size_t)r * 128 + q * 4);
        split4(v, Bh + r * BLD + q * 4, Bl + r * BLD + q * 4);
    }
    #pragma unroll
    for (int t = tid; t < 2048; t += 256) biasT[t] = __ldg(bias + (t & 127));
    {
        const int wr = warp * 32;
        #pragma unroll
        for (int t = lane; t < 1024; t += 32) {
            int r = t >> 5, q = t & 31;
            int gr = rowbase + wr + r;
            float4 v = make_float4(0.f, 0.f, 0.f, 0.f);
            if (gr < n) v = *(const float4*)(A + (size_t)gr * 128 + q * 4);
            split4(v, Ah + (wr + r) * BLD + q * 4, Al + (wr + r) * BLD + q * 4);
        }
    }
    __syncthreads();

    wmma::fragment<wmma::accumulator, 16, 16, 16, float> acc[2][8];
    #pragma unroll
    for (int i = 0; i < 2; i++)
        #pragma unroll
        for (int j = 0; j < 8; j++)
            wmma::load_matrix_sync(acc[i][j], biasT + j * 16, 128, wmma::mem_row_major);

    #pragma unroll
    for (int ks = 0; ks < 8; ks++) {
        wmma::fragment<wmma::matrix_a, 16, 16, 16, __nv_bfloat16, wmma::row_major> ah[2], al[2];
        #pragma unroll
        for (int i = 0; i < 2; i++) {
            wmma::load_matrix_sync(ah[i], Ah + (warp * 32 + i * 16) * BLD + ks * 16, BLD);
            wmma::load_matrix_sync(al[i], Al + (warp * 32 + i * 16) * BLD + ks * 16, BLD);
        }
        #pragma unroll
        for (int j = 0; j < 8; j++) {
            wmma::fragment<wmma::matrix_b, 16, 16, 16, __nv_bfloat16, wmma::row_major> bh, bl;
            wmma::load_matrix_sync(bh, Bh + (ks * 16) * BLD + j * 16, BLD);
            wmma::load_matrix_sync(bl, Bl + (ks * 16) * BLD + j * 16, BLD);
            #pragma unroll
            for (int i = 0; i < 2; i++) {
                wmma::mma_sync(acc[i][j], ah[i], bh, acc[i][j]);
                wmma::mma_sync(acc[i][j], ah[i], bl, acc[i][j]);
                wmma::mma_sync(acc[i][j], al[i], bh, acc[i][j]);
            }
        }
    }

    if (rowbase + 256 <= n) {
        #pragma unroll
        for (int i = 0; i < 2; i++) {
            float* crow = C + (size_t)(rowbase + warp * 32 + i * 16) * 128;
            #pragma unroll
            for (int j = 0; j < 8; j++)
                wmma::store_matrix_sync(crow + j * 16, acc[i][j], 128, wmma::mem_row_major);
        }
    } else {
        __syncthreads();
        float* epi = (float*)(sm + SM_EPI);
        #pragma unroll
        for (int i = 0; i < 2; i++)
            #pragma unroll
            for (int j = 0; j < 8; j++)
                wmma::store_matrix_sync(epi + (warp * 32 + i * 16) * 128 + j * 16,
                                        acc[i][j], 128, wmma::mem_row_major);
        __syncthreads();
        #pragma unroll
        for (int t = tid; t < 8192; t += 256) {
            int r = t >> 5, q = t & 31;
            int gr = rowbase + r;
            if (gr < n)
                *(float4*)(C + (size_t)gr * 128 + q * 4) = *(const float4*)(epi + r * 128 + q * 4);
        }
    }
}

// ---------------- edge kernels (unchanged, proven) ----------------
__global__ void init_agg(float* __restrict__ agg, const float* __restrict__ bias,
                         float* __restrict__ ssum, int n)
{
    size_t i = blockIdx.x * (size_t)blockDim.x + threadIdx.x;
    if (i < (size_t)n * 128) agg[i] = bias[i & 127];
    if (i < (size_t)n * 4) ssum[i] = 0.f;
}

__global__ void edge_pass1(const int* __restrict__ src, const int* __restrict__ dst,
                           const float* __restrict__ el, const float* __restrict__ er,
                           float* __restrict__ exb, float* __restrict__ ssum, int ne)
{
    int e = blockIdx.x * blockDim.x + threadIdx.x;
    if (e >= ne) return;
    int s = src[e], d = dst[e];
    float4 a = ((const float4*)el)[s];
    float4 b = ((const float4*)er)[d];
    float4 x;
    x.x = lrelu_exp(a.x + b.x);
    x.y = lrelu_exp(a.y + b.y);
    x.z = lrelu_exp(a.z + b.z);
    x.w = lrelu_exp(a.w + b.w);
    ((float4*)exb)[e] = x;
    red_add_v4(ssum + (size_t)d * 4, x);
}

__global__ void edge_pass2(const int* __restrict__ src, const int* __restrict__ dst,
                           const float* __restrict__ exb, const float* __restrict__ ssum,
                           const float* __restrict__ fs, float* __restrict__ agg, int ne)
{
    int w = (int)((blockIdx.x * (size_t)blockDim.x + threadIdx.x) >> 5);
    int lane = threadIdx.x & 31;
    if (w >= ne) return;
    int s = src[w], d = dst[w];
    int head = lane >> 3;
    float a = exb[(size_t)w * 4 + head] / ssum[(size_t)d * 4 + head];
    float4 f = ((const float4*)fs)[(size_t)s * 32 + lane];
    float4 m = make_float4(a * f.x, a * f.y, a * f.z, a * f.w);
    red_add_v4(agg + (size_t)d * 128 + lane * 4, m);
}

// ---------------- launch ----------------
extern "C" void kernel_launch(void* const* d_in, const int* in_sizes, int n_in,
                              void* d_out, int out_size)
{
    const float* x_drug  = (const float*)d_in[0];
    const float* x_prot  = (const float*)d_in[1];
    const int*   src_dp  = (const int*)d_in[2];
    const int*   dst_dp  = (const int*)d_in[3];
    const int*   src_pd  = (const int*)d_in[4];
    const int*   dst_pd  = (const int*)d_in[5];
    const float* W_in_d  = (const float*)d_in[6];
    const float* b_in_d  = (const float*)d_in[7];
    const float* W_in_p  = (const float*)d_in[8];
    const float* b_in_p  = (const float*)d_in[9];
    const float* W_dp    = (const float*)d_in[10];
    const float* al_dp   = (const float*)d_in[11];
    const float* ar_dp   = (const float*)d_in[12];
    const float* bias_dp = (const float*)d_in[13];
    const float* W_pd    = (const float*)d_in[14];
    const float* al_pd   = (const float*)d_in[15];
    const float* ar_pd   = (const float*)d_in[16];
    const float* bias_pd = (const float*)d_in[17];
    const float* W_out_d = (const float*)d_in[18];
    const float* b_out_d = (const float*)d_in[19];
    const float* W_out_p = (const float*)d_in[20];
    const float* b_out_p = (const float*)d_in[21];
    float* out = (float*)d_out;

    float *fs_dp, *fs_pd, *agg_p, *agg_d;
    float *el_dp, *er_dp, *el_pd, *er_pd, *s_p, *s_d, *ex_dp, *ex_pd;
    cudaGetSymbolAddress((void**)&fs_dp, g_fs_dp);
    cudaGetSymbolAddress((void**)&fs_pd, g_fs_pd);
    cudaGetSymbolAddress((void**)&agg_p, g_agg_p);
    cudaGetSymbolAddress((void**)&agg_d, g_agg_d);
    cudaGetSymbolAddress((void**)&el_dp, g_el_dp);
    cudaGetSymbolAddress((void**)&er_dp, g_er_dp);
    cudaGetSymbolAddress((void**)&el_pd, g_el_pd);
    cudaGetSymbolAddress((void**)&er_pd, g_er_pd);
    cudaGetSymbolAddress((void**)&s_p,   g_s_p);
    cudaGetSymbolAddress((void**)&s_d,   g_s_d);
    cudaGetSymbolAddress((void**)&ex_dp, g_ex_dp);
    cudaGetSymbolAddress((void**)&ex_pd, g_ex_pd);

    cudaFuncSetAttribute(fused_node, cudaFuncAttributeMaxDynamicSharedMemorySize, F_SMEM);
    cudaFuncSetAttribute(gemm_bf16, cudaFuncAttributeMaxDynamicSharedMemorySize, GW_SMEM);

    const int fb  = (ND + 127) / 128;   // 782 (ND == NP)
    const int gb  = (ND + 255) / 256;   // 391
    const int iaB = (int)(((size_t)ND * 128 + 255) / 256);
    const int e1B = (EE + 255) / 256;
    const int e2B = (int)(((size_t)EE * 32 + 255) / 256);

    // fused front end:
    // drug: T=relu(x_d@W_in_d+b); fs_dp=T@W_dp (write, el_dp); V=T@W_pd (er_pd only)
    fused_node<<<fb, 256, F_SMEM>>>(x_drug, W_in_d, b_in_d,
                                    W_dp, al_dp, W_pd, ar_pd,
                                    fs_dp, el_dp, er_pd, ND);
    // prot: T=relu(x_p@W_in_p+b); fs_pd=T@W_pd (write, el_pd); V=T@W_dp (er_dp only)
    fused_node<<<fb, 256, F_SMEM>>>(x_prot, W_in_p, b_in_p,
                                    W_pd, al_pd, W_dp, ar_dp,
                                    fs_pd, el_pd, er_dp, NP);
    // aggregation buffers (agg preloaded with GAT bias) + denominators
    init_agg<<<iaB, 256>>>(agg_p, bias_dp, s_p, NP);
    init_agg<<<iaB, 256>>>(agg_d, bias_pd, s_d, ND);
    // edge softmax + weighted aggregation
    edge_pass1<<<e1B, 256>>>(src_dp, dst_dp, el_dp, er_dp, ex_dp, s_p, EE);
    edge_pass1<<<e1B, 256>>>(src_pd, dst_pd, el_pd, er_pd, ex_pd, s_d, EE);
    edge_pass2<<<e2B, 256>>>(src_dp, dst_dp, ex_dp, s_p, fs_dp, agg_p, EE);
    edge_pass2<<<e2B, 256>>>(src_pd, dst_pd, ex_pd, s_d, fs_pd, agg_d, EE);
    // output projections
    gemm_bf16<<<gb, 256, GW_SMEM>>>(agg_d, W_out_d, b_out_d, out, ND);
    gemm_bf16<<<gb, 256, GW_SMEM>>>(agg_p, W_out_p, b_out_p, out + (size_t)ND * 128, NP);
}

// round 17
// speedup vs baseline: 1.0294x; 1.0294x over previous
#include <cuda_runtime.h>
#include <cuda_bf16.h>
#include <math.h>
#include <stdint.h>
#include <mma.h>

using namespace nvcuda;

#define ND 100000
#define NP 100000
#define EE 800000

// ---------------- scratch (__device__ globals; no allocations) ----------------
__device__ float g_hd[ND * 128];
__device__ float g_hp[NP * 128];
__device__ float g_fs_dp[ND * 128];
__device__ float g_fs_pd[NP * 128];
__device__ float g_agg_p[NP * 128];
__device__ float g_agg_d[ND * 128];
__device__ float g_el_dp[ND * 4];
__device__ float g_er_dp[NP * 4];
__device__ float g_el_pd[NP * 4];
__device__ float g_er_pd[ND * 4];
__device__ float g_s_p[NP * 4];
__device__ float g_s_d[ND * 4];
__device__ float g_ex_dp[EE * 4];
__device__ float g_ex_pd[EE * 4];
__device__ float g_ebias_d[128];
__device__ float g_ebias_p[128];
__device__ float g_scrap[ND * 4];   // dummy sink/source for unused kernel args

// ---------------- helpers ----------------
__device__ __forceinline__ void red_add_v4(float* addr, float4 v) {
    asm volatile("red.global.add.v4.f32 [%0], {%1,%2,%3,%4};"
                 :: "l"(addr), "f"(v.x), "f"(v.y), "f"(v.z), "f"(v.w) : "memory");
}
__device__ __forceinline__ float lrelu_exp(float v) {
    // leaky_relu(v,0.2) then exp; softmax max-shift omitted (shift-invariant, |e| = O(1))
    return expf(v > 0.f ? v : 0.2f * v);
}

// split v into bf16 hi + bf16 lo (v ~= hi + lo), store 4 consecutive
__device__ __forceinline__ void split4(float4 v, __nv_bfloat16* hi, __nv_bfloat16* lo) {
    __nv_bfloat16 h0 = __float2bfloat16(v.x);
    __nv_bfloat16 h1 = __float2bfloat16(v.y);
    __nv_bfloat16 h2 = __float2bfloat16(v.z);
    __nv_bfloat16 h3 = __float2bfloat16(v.w);
    __nv_bfloat16 l0 = __float2bfloat16(v.x - __bfloat162float(h0));
    __nv_bfloat16 l1 = __float2bfloat16(v.y - __bfloat162float(h1));
    __nv_bfloat16 l2 = __float2bfloat16(v.z - __bfloat162float(h2));
    __nv_bfloat16 l3 = __float2bfloat16(v.w - __bfloat162float(h3));
    __nv_bfloat162* H = (__nv_bfloat162*)hi;
    __nv_bfloat162* L = (__nv_bfloat162*)lo;
    H[0] = __nv_bfloat162(h0, h1); H[1] = __nv_bfloat162(h2, h3);
    L[0] = __nv_bfloat162(l0, l1); L[1] = __nv_bfloat162(l2, l3);
}

// grid-stride float4 zero fill (n4 = element count / 4)
__global__ void zero_k(float4* __restrict__ p, int n4)
{
    int i = blockIdx.x * blockDim.x + threadIdx.x;
    int stride = gridDim.x * blockDim.x;
    float4 z = make_float4(0.f, 0.f, 0.f, 0.f);
    for (; i < n4; i += stride) p[i] = z;
}

// effective out-projection bias: eb[j] = bout[j] + sum_k gatbias[k] * W[k][j]
__global__ void ebias_k(const float* __restrict__ gatbias, const float* __restrict__ W,
                        const float* __restrict__ bout, float* __restrict__ eb)
{
    int j = threadIdx.x;
    float s = bout[j];
    #pragma unroll 8
    for (int k = 0; k < 128; k++) s += gatbias[k] * W[k * 128 + j];
    eb[j] = s;
}

// ---------------- bf16 wmma GEMM (3-term split), modes:
//  0: C = A@B + bias
//  1: C = relu(A@B + bias)
//  2: C = A@B;  attn_out[r][h] = dot(C_row_head, attv)   (fs projections)
//  3: attn_out only, C not written                        (fd projections)
// All pointer args must be valid device pointers at every call site (mode
// decides which are actually used).
#define BLD 136
#define SM_BH 0
#define SM_BL (128 * BLD * 2)
#define SM_AH (2 * 128 * BLD * 2)
#define SM_AL (SM_AH + 256 * BLD * 2)
#define SM_BIAS (SM_AH + 2 * 256 * BLD * 2)   // bias 16x128 f32 OR att vector
#define SM_EPI SM_AH                          // epilogue bounce region (256*128*4 = 128KB)
#define GW_SMEM (SM_BIAS + 16 * 128 * 4)

__global__ void __launch_bounds__(256, 1)
gemm_bf16(const float* __restrict__ A, const float* __restrict__ B,
          const float* __restrict__ bias, float* __restrict__ C,
          float* __restrict__ attn_out, const float* __restrict__ attv,
          int n, int mode)
{
    extern __shared__ char sm[];
    __nv_bfloat16* Bh = (__nv_bfloat16*)(sm + SM_BH);
    __nv_bfloat16* Bl = (__nv_bfloat16*)(sm + SM_BL);
    __nv_bfloat16* Ah = (__nv_bfloat16*)(sm + SM_AH);
    __nv_bfloat16* Al = (__nv_bfloat16*)(sm + SM_AL);
    float* biasT = (float*)(sm + SM_BIAS);
    float* att = (float*)(sm + SM_BIAS);

    const int tid = threadIdx.x;
    const int warp = tid >> 5;
    const int lane = tid & 31;
    const int rowbase = blockIdx.x * 256;

    #pragma unroll
    for (int t = tid; t < 4096; t += 256) {
        int r = t >> 5, q = t & 31;
        float4 v = *(const float4*)(B + (size_t)r * 128 + q * 4);
        split4(v, Bh + r * BLD + q * 4, Bl + r * BLD + q * 4);
    }
    if (mode <= 1) {
        #pragma unroll
        for (int t = tid; t < 2048; t += 256) biasT[t] = __ldg(bias + (t & 127));
    } else {
        if (tid < 128) att[tid] = __ldg(attv + tid);
    }
    {
        const int wr = warp * 32;
        #pragma unroll
        for (int t = lane; t < 1024; t += 32) {
            int r = t >> 5, q = t & 31;
            int gr = rowbase + wr + r;
            float4 v = make_float4(0.f, 0.f, 0.f, 0.f);
            if (gr < n) v = *(const float4*)(A + (size_t)gr * 128 + q * 4);
            split4(v, Ah + (wr + r) * BLD + q * 4, Al + (wr + r) * BLD + q * 4);
        }
    }
    __syncthreads();

    wmma::fragment<wmma::accumulator, 16, 16, 16, float> acc[2][8];
    if (mode <= 1) {
        #pragma unroll
        for (int i = 0; i < 2; i++)
            #pragma unroll
            for (int j = 0; j < 8; j++)
                wmma::load_matrix_sync(acc[i][j], biasT + j * 16, 128, wmma::mem_row_major);
    } else {
        #pragma unroll
        for (int i = 0; i < 2; i++)
            #pragma unroll
            for (int j = 0; j < 8; j++)
                wmma::fill_fragment(acc[i][j], 0.f);
    }

    #pragma unroll
    for (int ks = 0; ks < 8; ks++) {
        wmma::fragment<wmma::matrix_a, 16, 16, 16, __nv_bfloat16, wmma::row_major> ah[2], al[2];
        #pragma unroll
        for (int i = 0; i < 2; i++) {
            wmma::load_matrix_sync(ah[i], Ah + (warp * 32 + i * 16) * BLD + ks * 16, BLD);
            wmma::load_matrix_sync(al[i], Al + (warp * 32 + i * 16) * BLD + ks * 16, BLD);
        }
        #pragma unroll
        for (int j = 0; j < 8; j++) {
            wmma::fragment<wmma::matrix_b, 16, 16, 16, __nv_bfloat16, wmma::row_major> bh, bl;
            wmma::load_matrix_sync(bh, Bh + (ks * 16) * BLD + j * 16, BLD);
            wmma::load_matrix_sync(bl, Bl + (ks * 16) * BLD + j * 16, BLD);
            #pragma unroll
            for (int i = 0; i < 2; i++) {
                wmma::mma_sync(acc[i][j], ah[i], bh, acc[i][j]);
                wmma::mma_sync(acc[i][j], ah[i], bl, acc[i][j]);
                wmma::mma_sync(acc[i][j], al[i], bh, acc[i][j]);
            }
        }
    }

    if (mode == 1) {
        #pragma unroll
        for (int i = 0; i < 2; i++)
            #pragma unroll
            for (int j = 0; j < 8; j++)
                #pragma unroll
                for (int t = 0; t < acc[i][j].num_elements; t++)
                    acc[i][j].x[t] = fmaxf(acc[i][j].x[t], 0.f);
    }

    if (mode <= 1) {
        if (rowbase + 256 <= n) {
            #pragma unroll
            for (int i = 0; i < 2; i++) {
                float* crow = C + (size_t)(rowbase + warp * 32 + i * 16) * 128;
                #pragma unroll
                for (int j = 0; j < 8; j++)
                    wmma::store_matrix_sync(crow + j * 16, acc[i][j], 128, wmma::mem_row_major);
            }
        } else {
            __syncthreads();
            float* epi = (float*)(sm + SM_EPI);
            #pragma unroll
            for (int i = 0; i < 2; i++)
                #pragma unroll
                for (int j = 0; j < 8; j++)
                    wmma::store_matrix_sync(epi + (warp * 32 + i * 16) * 128 + j * 16,
                                            acc[i][j], 128, wmma::mem_row_major);
            __syncthreads();
            #pragma unroll
            for (int t = tid; t < 8192; t += 256) {
                int r = t >> 5, q = t & 31;
                int gr = rowbase + r;
                if (gr < n)
                    *(float4*)(C + (size_t)gr * 128 + q * 4) =
                        *(const float4*)(epi + r * 128 + q * 4);
            }
        }
    } else {
        // modes 2/3: bounce through smem; write C (mode 2) and headdot -> attn_out
        __syncthreads();
        float* epi = (float*)(sm + SM_EPI);
        #pragma unroll
        for (int i = 0; i < 2; i++)
            #pragma unroll
            for (int j = 0; j < 8; j++)
                wmma::store_matrix_sync(epi + (warp * 32 + i * 16) * 128 + j * 16,
                                        acc[i][j], 128, wmma::mem_row_major);
        __syncthreads();
        if (mode == 2) {
            #pragma unroll
            for (int t = tid; t < 8192; t += 256) {
                int r = t >> 5, q = t & 31;
                int gr = rowbase + r;
                if (gr < n)
                    *(float4*)(C + (size_t)gr * 128 + q * 4) =
                        *(const float4*)(epi + r * 128 + q * 4);
            }
        }
        #pragma unroll
        for (int t = tid; t < 1024; t += 256) {
            int r = t >> 2, h = t & 3;
            int gr = rowbase + r;
            const float* row = epi + r * 128 + h * 32;
            const float* av = att + h * 32;
            float s = 0.f;
            #pragma unroll
            for (int d = 0; d < 32; d++) s += row[d] * av[d];
            if (gr < n) attn_out[(size_t)gr * 4 + h] = s;
        }
    }
}

// ---------------- edge kernels (unchanged, proven) ----------------
__global__ void edge_pass1(const int* __restrict__ src, const int* __restrict__ dst,
                           const float* __restrict__ el, const float* __restrict__ er,
                           float* __restrict__ exb, float* __restrict__ ssum, int ne)
{
    int e = blockIdx.x * blockDim.x + threadIdx.x;
    if (e >= ne) return;
    int s = src[e], d = dst[e];
    float4 a = ((const float4*)el)[s];
    float4 b = ((const float4*)er)[d];
    float4 x;
    x.x = lrelu_exp(a.x + b.x);
    x.y = lrelu_exp(a.y + b.y);
    x.z = lrelu_exp(a.z + b.z);
    x.w = lrelu_exp(a.w + b.w);
    ((float4*)exb)[e] = x;
    red_add_v4(ssum + (size_t)d * 4, x);
}

__global__ void edge_pass2(const int* __restrict__ src, const int* __restrict__ dst,
                           const float* __restrict__ exb, const float* __restrict__ ssum,
                           const float* __restrict__ fs, float* __restrict__ agg, int ne)
{
    int w = (int)((blockIdx.x * (size_t)blockDim.x + threadIdx.x) >> 5);
    int lane = threadIdx.x & 31;
    if (w >= ne) return;
    int s = src[w], d = dst[w];
    int head = lane >> 3;
    float a = exb[(size_t)w * 4 + head] / ssum[(size_t)d * 4 + head];
    float4 f = ((const float4*)fs)[(size_t)s * 32 + lane];
    float4 m = make_float4(a * f.x, a * f.y, a * f.z, a * f.w);
    red_add_v4(agg + (size_t)d * 128 + lane * 4, m);
}

// ---------------- launch ----------------
extern "C" void kernel_launch(void* const* d_in, const int* in_sizes, int n_in,
                              void* d_out, int out_size)
{
    const float* x_drug  = (const float*)d_in[0];
    const float* x_prot  = (const float*)d_in[1];
    const int*   src_dp  = (const int*)d_in[2];
    const int*   dst_dp  = (const int*)d_in[3];
    const int*   src_pd  = (const int*)d_in[4];
    const int*   dst_pd  = (const int*)d_in[5];
    const float* W_in_d  = (const float*)d_in[6];
    const float* b_in_d  = (const float*)d_in[7];
    const float* W_in_p  = (const float*)d_in[8];
    const float* b_in_p  = (const float*)d_in[9];
    const float* W_dp    = (const float*)d_in[10];
    const float* al_dp   = (const float*)d_in[11];
    const float* ar_dp   = (const float*)d_in[12];
    const float* bias_dp = (const float*)d_in[13];
    const float* W_pd    = (const float*)d_in[14];
    const float* al_pd   = (const float*)d_in[15];
    const float* ar_pd   = (const float*)d_in[16];
    const float* bias_pd = (const float*)d_in[17];
    const float* W_out_d = (const float*)d_in[18];
    const float* b_out_d = (const float*)d_in[19];
    const float* W_out_p = (const float*)d_in[20];
    const float* b_out_p = (const float*)d_in[21];
    float* out = (float*)d_out;

    float *hd, *hp, *fs_dp, *fs_pd, *agg_p, *agg_d;
    float *el_dp, *er_dp, *el_pd, *er_pd, *s_p, *s_d, *ex_dp, *ex_pd;
    float *eb_d, *eb_p, *scrap;
    cudaGetSymbolAddress((void**)&hd,    g_hd);
    cudaGetSymbolAddress((void**)&hp,    g_hp);
    cudaGetSymbolAddress((void**)&fs_dp, g_fs_dp);
    cudaGetSymbolAddress((void**)&fs_pd, g_fs_pd);
    cudaGetSymbolAddress((void**)&agg_p, g_agg_p);
    cudaGetSymbolAddress((void**)&agg_d, g_agg_d);
    cudaGetSymbolAddress((void**)&el_dp, g_el_dp);
    cudaGetSymbolAddress((void**)&er_dp, g_er_dp);
    cudaGetSymbolAddress((void**)&el_pd, g_el_pd);
    cudaGetSymbolAddress((void**)&er_pd, g_er_pd);
    cudaGetSymbolAddress((void**)&s_p,   g_s_p);
    cudaGetSymbolAddress((void**)&s_d,   g_s_d);
    cudaGetSymbolAddress((void**)&ex_dp, g_ex_dp);
    cudaGetSymbolAddress((void**)&ex_pd, g_ex_pd);
    cudaGetSymbolAddress((void**)&eb_d,  g_ebias_d);
    cudaGetSymbolAddress((void**)&eb_p,  g_ebias_p);
    cudaGetSymbolAddress((void**)&scrap, g_scrap);

    cudaFuncSetAttribute(gemm_bf16, cudaFuncAttributeMaxDynamicSharedMemorySize, GW_SMEM);

    const int gb  = (ND + 255) / 256;   // 391 (ND == NP)
    const int e1B = (EE + 255) / 256;
    const int e2B = (int)(((size_t)EE * 32 + 255) / 256);

    // zero aggregation buffers + softmax denominators (vectorized fill kernels)
    zero_k<<<1280, 256>>>((float4*)agg_p, ND * 32);
    zero_k<<<1280, 256>>>((float4*)agg_d, ND * 32);
    zero_k<<<128, 256>>>((float4*)s_p, NP);
    zero_k<<<128, 256>>>((float4*)s_d, ND);
    // effective out-projection biases (fold GAT bias through W_out)
    ebias_k<<<1, 128>>>(bias_pd, W_out_d, b_out_d, eb_d);   // drugs receive etype pd
    ebias_k<<<1, 128>>>(bias_dp, W_out_p, b_out_p, eb_p);   // prots receive etype dp

    // input projections + relu (mode 1: attn args unused, pass scrap)
    gemm_bf16<<<gb, 256, GW_SMEM>>>(x_drug, W_in_d, b_in_d, hd, scrap, eb_d, ND, 1);
    gemm_bf16<<<gb, 256, GW_SMEM>>>(x_prot, W_in_p, b_in_p, hp, scrap, eb_p, NP, 1);
    // fs projections (mode 2: bias arg unused, pass eb; write fs + el in-epilogue)
    gemm_bf16<<<gb, 256, GW_SMEM>>>(hd, W_dp, eb_d, fs_dp, el_dp, al_dp, ND, 2);
    gemm_bf16<<<gb, 256, GW_SMEM>>>(hp, W_pd, eb_p, fs_pd, el_pd, al_pd, NP, 2);
    // fd projections (mode 3: bias + C unused, pass eb/scrap; er only, fd never stored)
    gemm_bf16<<<gb, 256, GW_SMEM>>>(hp, W_dp, eb_p, scrap, er_dp, ar_dp, NP, 3);
    gemm_bf16<<<gb, 256, GW_SMEM>>>(hd, W_pd, eb_d, scrap, er_pd, ar_pd, ND, 3);
    // edge softmax + weighted aggregation
    edge_pass1<<<e1B, 256>>>(src_dp, dst_dp, el_dp, er_dp, ex_dp, s_p, EE);
    edge_pass1<<<e1B, 256>>>(src_pd, dst_pd, el_pd, er_pd, ex_pd, s_d, EE);
    edge_pass2<<<e2B, 256>>>(src_dp, dst_dp, ex_dp, s_p, fs_dp, agg_p, EE);
    edge_pass2<<<e2B, 256>>>(src_pd, dst_pd, ex_pd, s_d, fs_pd, agg_d, EE);
    // output projections with folded bias (modes 0: attn args unused, pass scrap)
    gemm_bf16<<<gb, 256, GW_SMEM>>>(agg_d, W_out_d, eb_d, out, scrap, eb_d, ND, 0);
    gemm_bf16<<<gb, 256, GW_SMEM>>>(agg_p, W_out_p, eb_p, out + (size_t)ND * 128, scrap, eb_p, NP, 0);
}